// round 1
// baseline (speedup 1.0000x reference)
#include <cuda_runtime.h>
#include <cuda_bf16.h>

// Scratch (allocation-free rule: __device__ globals)
__device__ float g_qkv[4 * 384 * 2304];   // (b, 384, N) : q=0..127, k=128..255, v=256..383
__device__ float g_attn[4 * 128 * 2304];  // (b, 8, N, 16) contiguous == (b,128,N) reinterpret

#define N_SP 2304   // 48*48
#define ICC 8

// ---------------------------------------------------------------------------
// Kernel 1: 3x3 circular conv for both w_init (->d_out ch 0..127) and
//           w_qkv (->g_qkv ch 0..383). Block = (b,row,ocg of 64 oc).
// ---------------------------------------------------------------------------
__global__ __launch_bounds__(256) void conv3x3_kernel(
    const float* __restrict__ x, const float* __restrict__ w_init,
    const float* __restrict__ w_qkv, float* __restrict__ out)
{
    extern __shared__ float sm[];
    float* x_s = sm;                 // [3][128][50] row halo
    float* w_s = sm + 3 * 128 * 50;  // [64][ICC][9]

    const int b   = blockIdx.z;
    const int row = blockIdx.y;
    const int ocg = blockIdx.x;      // 0..7
    const int tid = threadIdx.x;

    // Load x tile: 3 wrapped rows, all 128 ic, 50 cols (circular halo)
    for (int i = tid; i < 3 * 128 * 50; i += 256) {
        int kh  = i / (128 * 50);
        int rem = i - kh * 128 * 50;
        int ic  = rem / 50;
        int cc  = rem - ic * 50;
        int srow = row + kh - 1; srow = (srow + 48) % 48;
        int scol = cc - 1;       scol = (scol + 48) % 48;
        x_s[i] = x[((b * 128 + ic) * 48 + srow) * 48 + scol];
    }

    const int oc_l = tid >> 2;          // 0..63
    const int col0 = (tid & 3) * 12;    // 0,12,24,36
    const int oc_g = ocg * 64 + oc_l;   // 0..511

    float acc[12];
    #pragma unroll
    for (int j = 0; j < 12; j++) acc[j] = 0.f;

    for (int chunk = 0; chunk < 128 / ICC; chunk++) {
        __syncthreads();
        // stage weights for this ic chunk
        for (int i = tid; i < 64 * ICC * 9; i += 256) {
            int wo  = i / (ICC * 9);
            int rem = i - wo * (ICC * 9);
            int ici = rem / 9;
            int k   = rem - ici * 9;
            int ocw = ocg * 64 + wo;
            int ic  = chunk * ICC + ici;
            w_s[i] = (ocw < 128) ? w_init[(ocw * 128 + ic) * 9 + k]
                                 : w_qkv[((ocw - 128) * 128 + ic) * 9 + k];
        }
        __syncthreads();

        #pragma unroll 2
        for (int ici = 0; ici < ICC; ici++) {
            const int ic = chunk * ICC + ici;
            const float* wr = &w_s[(oc_l * ICC + ici) * 9];
            #pragma unroll
            for (int kh = 0; kh < 3; kh++) {
                const float2* xp = (const float2*)&x_s[(kh * 128 + ic) * 50 + col0];
                float xv[14];
                #pragma unroll
                for (int t = 0; t < 7; t++) {
                    float2 v = xp[t];
                    xv[2 * t] = v.x; xv[2 * t + 1] = v.y;
                }
                const float wa = wr[kh * 3 + 0];
                const float wb = wr[kh * 3 + 1];
                const float wc = wr[kh * 3 + 2];
                #pragma unroll
                for (int j = 0; j < 12; j++)
                    acc[j] += wa * xv[j] + wb * xv[j + 1] + wc * xv[j + 2];
            }
        }
    }

    float* dst = (oc_g < 128)
        ? out   + (b * 256 + oc_g) * N_SP + row * 48 + col0
        : g_qkv + (b * 384 + (oc_g - 128)) * N_SP + row * 48 + col0;
    #pragma unroll
    for (int j = 0; j < 12; j++) dst[j] = acc[j];
}

// ---------------------------------------------------------------------------
// Kernel 2: per-(b,h) attention, flash-style online softmax.
// One query per thread; K/V tiles (16x256 each) staged in SMEM.
// ---------------------------------------------------------------------------
__global__ __launch_bounds__(256) void attn_kernel()
{
    __shared__ float k_s[16 * 256];
    __shared__ float v_s[16 * 256];

    const int b = blockIdx.z, h = blockIdx.y;
    const int tid = threadIdx.x;
    const int n = blockIdx.x * 256 + tid;

    const float* base = g_qkv + (b * 384) * N_SP;
    const float scale = 0.25f;  // 16^-0.5

    float q[16];
    #pragma unroll
    for (int d = 0; d < 16; d++) q[d] = base[(h * 16 + d) * N_SP + n] * scale;

    float mx = -1e30f, sum = 0.f;
    float acc[16];
    #pragma unroll
    for (int d = 0; d < 16; d++) acc[d] = 0.f;

    for (int mt = 0; mt < 9; mt++) {
        __syncthreads();
        for (int i = tid; i < 4096; i += 256) {
            int d = i >> 8, m = i & 255;
            k_s[i] = base[(128 + h * 16 + d) * N_SP + mt * 256 + m];
            v_s[i] = base[(256 + h * 16 + d) * N_SP + mt * 256 + m];
        }
        __syncthreads();

        for (int mm = 0; mm < 256; mm += 4) {
            float d0 = 0.f, d1 = 0.f, d2 = 0.f, d3 = 0.f;
            #pragma unroll
            for (int d = 0; d < 16; d++) {
                float4 kv = *(const float4*)&k_s[d * 256 + mm];
                d0 += q[d] * kv.x; d1 += q[d] * kv.y;
                d2 += q[d] * kv.z; d3 += q[d] * kv.w;
            }
            float tmax = fmaxf(fmaxf(d0, d1), fmaxf(d2, d3));
            if (tmax > mx) {
                float c = __expf(mx - tmax);
                sum *= c;
                #pragma unroll
                for (int d = 0; d < 16; d++) acc[d] *= c;
                mx = tmax;
            }
            float p0 = __expf(d0 - mx), p1 = __expf(d1 - mx);
            float p2 = __expf(d2 - mx), p3 = __expf(d3 - mx);
            sum += (p0 + p1) + (p2 + p3);
            #pragma unroll
            for (int d = 0; d < 16; d++) {
                float4 vv = *(const float4*)&v_s[d * 256 + mm];
                acc[d] += p0 * vv.x + p1 * vv.y + p2 * vv.z + p3 * vv.w;
            }
        }
    }

    const float inv = 1.f / sum;
    float* dst = g_attn + ((b * 8 + h) * N_SP + n) * 16;  // (b,h,n,d) contiguous
    #pragma unroll
    for (int d = 0; d < 16; d++) dst[d] = acc[d] * inv;
}

// ---------------------------------------------------------------------------
// Kernel 3: 1x1 projection of reinterpreted attn (b,128,N) -> d_out ch 128..255
// ---------------------------------------------------------------------------
__global__ __launch_bounds__(256) void proj1x1_kernel(
    const float* __restrict__ w_out, float* __restrict__ out)
{
    extern __shared__ float sm[];
    float* w_s = sm;            // [ic][oc] transposed, 128x128
    float* a_s = sm + 16384;    // [ic][32]

    const int b  = blockIdx.y;
    const int s0 = blockIdx.x * 32;
    const int tid = threadIdx.x;

    for (int i = tid; i < 16384; i += 256) {
        int oc = i >> 7, ic = i & 127;
        w_s[ic * 128 + oc] = w_out[i];
    }
    for (int i = tid; i < 4096; i += 256) {
        int ic = i >> 5, j = i & 31;
        a_s[i] = g_attn[(b * 128 + ic) * N_SP + s0 + j];
    }
    __syncthreads();

    const int oc   = tid & 127;
    const int half = tid >> 7;  // warps 0-3 -> 0, warps 4-7 -> 1
    float acc[16];
    #pragma unroll
    for (int j = 0; j < 16; j++) acc[j] = 0.f;

    for (int ic = 0; ic < 128; ic++) {
        float w = w_s[ic * 128 + oc];
        const float4* ap = (const float4*)&a_s[ic * 32 + half * 16];
        #pragma unroll
        for (int t = 0; t < 4; t++) {
            float4 a = ap[t];
            acc[4 * t + 0] += w * a.x; acc[4 * t + 1] += w * a.y;
            acc[4 * t + 2] += w * a.z; acc[4 * t + 3] += w * a.w;
        }
    }

    float* dst = out + (b * 256 + 128 + oc) * N_SP + s0 + half * 16;
    #pragma unroll
    for (int j = 0; j < 16; j++) dst[j] = acc[j];
}

// ---------------------------------------------------------------------------
extern "C" void kernel_launch(void* const* d_in, const int* in_sizes, int n_in,
                              void* d_out, int out_size)
{
    const float* x      = (const float*)d_in[0];
    const float* w_init = (const float*)d_in[1];
    const float* w_qkv  = (const float*)d_in[2];
    const float* w_out  = (const float*)d_in[3];
    float* out = (float*)d_out;

    const int conv_smem = (3 * 128 * 50 + 64 * ICC * 9) * 4;  // 95232 B
    const int proj_smem = (16384 + 4096) * 4;                 // 81920 B
    cudaFuncSetAttribute(conv3x3_kernel,
                         cudaFuncAttributeMaxDynamicSharedMemorySize, conv_smem);
    cudaFuncSetAttribute(proj1x1_kernel,
                         cudaFuncAttributeMaxDynamicSharedMemorySize, proj_smem);

    dim3 cg(8, 48, 4);
    conv3x3_kernel<<<cg, 256, conv_smem>>>(x, w_init, w_qkv, out);

    dim3 ag(9, 8, 4);
    attn_kernel<<<ag, 256>>>();

    dim3 pg(72, 4);
    proj1x1_kernel<<<pg, 256, proj_smem>>>(w_out, out);
}

// round 2
// speedup vs baseline: 1.7958x; 1.7958x over previous
#include <cuda_runtime.h>
#include <cuda_bf16.h>
#include <cstdint>

// Scratch (allocation-free rule: __device__ globals)
__device__ float g_qkv[4 * 384 * 2304];   // (b, 384, N) : q=0..127, k=128..255, v=256..383
__device__ float g_attn[4 * 128 * 2304];  // (b, 8, N, 16) contiguous == (b,128,N) reinterpret
__device__ float g_w[9 * 512 * 128];      // weights transposed: [tap][oc][ic], tf32-rounded

#define N_SP 2304   // 48*48

// ---------------------------------------------------------------------------
// Kernel 0: transpose + tf32-convert weights: w[oc][ic][3][3] -> g_w[tap][oc][ic]
// ---------------------------------------------------------------------------
__global__ __launch_bounds__(1024) void wprep_kernel(
    const float* __restrict__ w_init, const float* __restrict__ w_qkv)
{
    int idx = blockIdx.x * 1024 + threadIdx.x;   // 9*512*128 = 589824 total
    int ic  = idx & 127;
    int oc  = (idx >> 7) & 511;
    int tap = idx >> 16;
    float v = (oc < 128) ? w_init[(oc * 128 + ic) * 9 + tap]
                         : w_qkv[((oc - 128) * 128 + ic) * 9 + tap];
    uint32_t t;
    asm("cvt.rna.tf32.f32 %0, %1;" : "=r"(t) : "f"(v));
    ((uint32_t*)g_w)[idx] = t;
}

// ---------------------------------------------------------------------------
// Kernel 1: 3x3 circular conv as 9-tap implicit GEMM on tensor cores (tf32).
// CTA: 128 oc x 96 pos (2 output rows). 8 warps: 4(M) x 2(N).
// Warp tile: 32 oc x 48 pos (one full output row) = 2 x 6 mma tiles m16n8k8.
// ---------------------------------------------------------------------------
#define XS_STRIDE 56     // padded floats per (row,ic): conflict-free B loads
#define WS_STRIDE 132    // padded floats per oc row:   conflict-free A loads
#define XS_FLOATS (4 * 128 * XS_STRIDE)
#define WS_FLOATS (128 * WS_STRIDE)

__device__ __forceinline__ void mma_tf32(float c[4], const uint32_t a[4],
                                         uint32_t b0, uint32_t b1)
{
    asm volatile(
        "mma.sync.aligned.m16n8k8.row.col.f32.tf32.tf32.f32 "
        "{%0,%1,%2,%3}, {%4,%5,%6,%7}, {%8,%9}, {%0,%1,%2,%3};"
        : "+f"(c[0]), "+f"(c[1]), "+f"(c[2]), "+f"(c[3])
        : "r"(a[0]), "r"(a[1]), "r"(a[2]), "r"(a[3]), "r"(b0), "r"(b1));
}

__global__ __launch_bounds__(256) void conv_mma_kernel(
    const float* __restrict__ x, float* __restrict__ out)
{
    extern __shared__ float sm[];
    float* x_s = sm;               // [4 rows][128 ic][56]
    float* w_s = sm + XS_FLOATS;   // [128 oc][132]

    const int b   = blockIdx.z;
    const int rp  = blockIdx.y;    // output row pair: rows 2rp, 2rp+1
    const int ocg = blockIdx.x;    // 0..3 (128 oc each)
    const int tid = threadIdx.x;
    const int wid = tid >> 5, lane = tid & 31;
    const int warp_m = wid & 3;    // oc offset 32 each
    const int warp_n = wid >> 2;   // output row within pair
    const int g = lane >> 2, q = lane & 3;

    // Stage x: 4 wrapped input rows, 128 ic, 50 cols (circular halo), tf32.
    for (int i = tid; i < 4 * 128 * 50; i += 256) {
        int r   = i / (128 * 50);
        int rem = i - r * 128 * 50;
        int ic  = rem / 50;
        int cc  = rem - ic * 50;
        int srow = (2 * rp - 1 + r + 48) % 48;
        int scol = (cc - 1 + 48) % 48;
        float v = x[((b * 128 + ic) * 48 + srow) * 48 + scol];
        uint32_t t;
        asm("cvt.rna.tf32.f32 %0, %1;" : "=r"(t) : "f"(v));
        ((uint32_t*)x_s)[(r * 128 + ic) * XS_STRIDE + cc] = t;
    }

    float c[2][6][4];
    #pragma unroll
    for (int mi = 0; mi < 2; mi++)
        #pragma unroll
        for (int j = 0; j < 6; j++)
            #pragma unroll
            for (int t = 0; t < 4; t++) c[mi][j][t] = 0.f;

    const uint32_t* xs = (const uint32_t*)x_s;
    const uint32_t* ws = (const uint32_t*)w_s;

    for (int tap = 0; tap < 9; tap++) {
        const int dr = tap / 3 - 1, dc = tap % 3 - 1;

        __syncthreads();
        // Stage this tap's weights: 128 oc x 128 ic, float4 vectorized.
        {
            const float4* src = (const float4*)(g_w + (tap * 512 + ocg * 128) * 128);
            #pragma unroll
            for (int i = 0; i < 16; i++) {
                int e4  = tid + i * 256;        // 4096 float4s
                int oc  = e4 >> 5;
                int ic4 = e4 & 31;
                float4 v = src[e4];
                *(float4*)&w_s[oc * WS_STRIDE + ic4 * 4] = v;
            }
        }
        __syncthreads();

        const int irow = warp_n + dr + 1;           // 0..3
        const int colb = dc + 1 + g;                // + j*8
        const uint32_t* xrow = xs + irow * 128 * XS_STRIDE;

        #pragma unroll
        for (int icc = 0; icc < 16; icc++) {
            const int ic0 = icc * 8;
            uint32_t a[2][4];
            #pragma unroll
            for (int mi = 0; mi < 2; mi++) {
                int r0 = (warp_m * 32 + mi * 16 + g) * WS_STRIDE + ic0 + q;
                a[mi][0] = ws[r0];
                a[mi][1] = ws[r0 + 8 * WS_STRIDE];
                a[mi][2] = ws[r0 + 4];
                a[mi][3] = ws[r0 + 8 * WS_STRIDE + 4];
            }
            #pragma unroll
            for (int j = 0; j < 6; j++) {
                uint32_t b0 = xrow[(ic0 + q) * XS_STRIDE + colb + j * 8];
                uint32_t b1 = xrow[(ic0 + q + 4) * XS_STRIDE + colb + j * 8];
                mma_tf32(c[0][j], a[0], b0, b1);
                mma_tf32(c[1][j], a[1], b0, b1);
            }
        }
    }

    // Write results. C element (r, n): c0,c1 at cols 2q,2q+1 (rows g, +8 for c2,c3).
    const int orow = 2 * rp + warp_n;
    const int spat = orow * 48;
    #pragma unroll
    for (int mi = 0; mi < 2; mi++) {
        int oc_l = ocg * 128 + warp_m * 32 + mi * 16 + g;  // global oc (0..511)
        float* p = (oc_l < 128)
            ? out   + (size_t)(b * 256 + oc_l) * N_SP
            : g_qkv + (size_t)(b * 384 + oc_l - 128) * N_SP;
        float* p8 = p + 8 * N_SP;   // row g+8 of same tile (oc_l+8 < boundary-safe: tiles of 16)
        #pragma unroll
        for (int j = 0; j < 6; j++) {
            int col = j * 8 + 2 * q;
            *(float2*)&p [spat + col] = make_float2(c[mi][j][0], c[mi][j][1]);
            *(float2*)&p8[spat + col] = make_float2(c[mi][j][2], c[mi][j][3]);
        }
    }
}

// ---------------------------------------------------------------------------
// Kernel 2: per-(b,h) attention, flash-style online softmax (fp32, unchanged).
// ---------------------------------------------------------------------------
__global__ __launch_bounds__(256) void attn_kernel()
{
    __shared__ float k_s[16 * 256];
    __shared__ float v_s[16 * 256];

    const int b = blockIdx.z, h = blockIdx.y;
    const int tid = threadIdx.x;
    const int n = blockIdx.x * 256 + tid;

    const float* base = g_qkv + (b * 384) * N_SP;
    const float scale = 0.25f;  // 16^-0.5

    float qv[16];
    #pragma unroll
    for (int d = 0; d < 16; d++) qv[d] = base[(h * 16 + d) * N_SP + n] * scale;

    float mx = -1e30f, sum = 0.f;
    float acc[16];
    #pragma unroll
    for (int d = 0; d < 16; d++) acc[d] = 0.f;

    for (int mt = 0; mt < 9; mt++) {
        __syncthreads();
        for (int i = tid; i < 4096; i += 256) {
            int d = i >> 8, m = i & 255;
            k_s[i] = base[(128 + h * 16 + d) * N_SP + mt * 256 + m];
            v_s[i] = base[(256 + h * 16 + d) * N_SP + mt * 256 + m];
        }
        __syncthreads();

        for (int mm = 0; mm < 256; mm += 4) {
            float d0 = 0.f, d1 = 0.f, d2 = 0.f, d3 = 0.f;
            #pragma unroll
            for (int d = 0; d < 16; d++) {
                float4 kv = *(const float4*)&k_s[d * 256 + mm];
                d0 += qv[d] * kv.x; d1 += qv[d] * kv.y;
                d2 += qv[d] * kv.z; d3 += qv[d] * kv.w;
            }
            float tmax = fmaxf(fmaxf(d0, d1), fmaxf(d2, d3));
            if (tmax > mx) {
                float cc = __expf(mx - tmax);
                sum *= cc;
                #pragma unroll
                for (int d = 0; d < 16; d++) acc[d] *= cc;
                mx = tmax;
            }
            float p0 = __expf(d0 - mx), p1 = __expf(d1 - mx);
            float p2 = __expf(d2 - mx), p3 = __expf(d3 - mx);
            sum += (p0 + p1) + (p2 + p3);
            #pragma unroll
            for (int d = 0; d < 16; d++) {
                float4 vv = *(const float4*)&v_s[d * 256 + mm];
                acc[d] += p0 * vv.x + p1 * vv.y + p2 * vv.z + p3 * vv.w;
            }
        }
    }

    const float inv = 1.f / sum;
    float* dst = g_attn + ((size_t)(b * 8 + h) * N_SP + n) * 16;  // (b,h,n,d)
    #pragma unroll
    for (int d = 0; d < 16; d++) dst[d] = acc[d] * inv;
}

// ---------------------------------------------------------------------------
// Kernel 3: 1x1 projection of reinterpreted attn (b,128,N) -> d_out ch 128..255
// ---------------------------------------------------------------------------
__global__ __launch_bounds__(256) void proj1x1_kernel(
    const float* __restrict__ w_out, float* __restrict__ out)
{
    extern __shared__ float sm[];
    float* w_s = sm;            // [ic][oc] transposed, 128x128
    float* a_s = sm + 16384;    // [ic][32]

    const int b  = blockIdx.y;
    const int s0 = blockIdx.x * 32;
    const int tid = threadIdx.x;

    for (int i = tid; i < 16384; i += 256) {
        int oc = i >> 7, ic = i & 127;
        w_s[ic * 128 + oc] = w_out[i];
    }
    for (int i = tid; i < 4096; i += 256) {
        int ic = i >> 5, j = i & 31;
        a_s[i] = g_attn[(b * 128 + ic) * N_SP + s0 + j];
    }
    __syncthreads();

    const int oc   = tid & 127;
    const int half = tid >> 7;
    float acc[16];
    #pragma unroll
    for (int j = 0; j < 16; j++) acc[j] = 0.f;

    for (int ic = 0; ic < 128; ic++) {
        float w = w_s[ic * 128 + oc];
        const float4* ap = (const float4*)&a_s[ic * 32 + half * 16];
        #pragma unroll
        for (int t = 0; t < 4; t++) {
            float4 a = ap[t];
            acc[4 * t + 0] += w * a.x; acc[4 * t + 1] += w * a.y;
            acc[4 * t + 2] += w * a.z; acc[4 * t + 3] += w * a.w;
        }
    }

    float* dst = out + (b * 256 + 128 + oc) * N_SP + s0 + half * 16;
    #pragma unroll
    for (int j = 0; j < 16; j++) dst[j] = acc[j];
}

// ---------------------------------------------------------------------------
extern "C" void kernel_launch(void* const* d_in, const int* in_sizes, int n_in,
                              void* d_out, int out_size)
{
    const float* x      = (const float*)d_in[0];
    const float* w_init = (const float*)d_in[1];
    const float* w_qkv  = (const float*)d_in[2];
    const float* w_out  = (const float*)d_in[3];
    float* out = (float*)d_out;

    const int conv_smem = (XS_FLOATS + WS_FLOATS) * 4;  // 182272 B
    const int proj_smem = (16384 + 4096) * 4;           // 81920 B
    cudaFuncSetAttribute(conv_mma_kernel,
                         cudaFuncAttributeMaxDynamicSharedMemorySize, conv_smem);
    cudaFuncSetAttribute(proj1x1_kernel,
                         cudaFuncAttributeMaxDynamicSharedMemorySize, proj_smem);

    wprep_kernel<<<576, 1024>>>(w_init, w_qkv);

    dim3 cg(4, 24, 4);
    conv_mma_kernel<<<cg, 256, conv_smem>>>(x, out);

    dim3 ag(9, 8, 4);
    attn_kernel<<<ag, 256>>>();

    dim3 pg(72, 4);
    proj1x1_kernel<<<pg, 256, proj_smem>>>(w_out, out);
}

// round 4
// speedup vs baseline: 3.1774x; 1.7693x over previous
#include <cuda_runtime.h>
#include <cuda_bf16.h>
#include <cstdint>

// Scratch (allocation-free rule: __device__ globals)
__device__ float g_qkv[4 * 384 * 2304];   // (b, 384, N) : q=0..127, k=128..255, v=256..383
__device__ float g_attn[4 * 128 * 2304];  // (b,8,N,16) contiguous == (b,128,N) reinterpret
__device__ float g_w[9 * 512 * 128];      // conv weights: [tap][oc][ic], tf32-rounded

#define N_SP 2304   // 48*48

__device__ __forceinline__ uint32_t to_tf32(float f) {
    uint32_t t;
    asm("cvt.rna.tf32.f32 %0, %1;" : "=r"(t) : "f"(f));
    return t;
}

__device__ __forceinline__ void mma_tf32(float c[4], const uint32_t a[4],
                                         uint32_t b0, uint32_t b1)
{
    asm volatile(
        "mma.sync.aligned.m16n8k8.row.col.f32.tf32.tf32.f32 "
        "{%0,%1,%2,%3}, {%4,%5,%6,%7}, {%8,%9}, {%0,%1,%2,%3};"
        : "+f"(c[0]), "+f"(c[1]), "+f"(c[2]), "+f"(c[3])
        : "r"(a[0]), "r"(a[1]), "r"(a[2]), "r"(a[3]), "r"(b0), "r"(b1));
}

// ---------------------------------------------------------------------------
// Kernel 0: transpose + tf32-convert conv weights
// ---------------------------------------------------------------------------
__global__ __launch_bounds__(1024) void wprep_kernel(
    const float* __restrict__ w_init, const float* __restrict__ w_qkv)
{
    int idx = blockIdx.x * 1024 + threadIdx.x;   // 9*512*128
    int ic  = idx & 127;
    int oc  = (idx >> 7) & 511;
    int tap = idx >> 16;
    float v = (oc < 128) ? w_init[(oc * 128 + ic) * 9 + tap]
                         : w_qkv[((oc - 128) * 128 + ic) * 9 + tap];
    ((uint32_t*)g_w)[idx] = to_tf32(v);
}

// ---------------------------------------------------------------------------
// Kernel 1: 3x3 circular conv as 9-tap implicit GEMM (tf32 mma).
// ---------------------------------------------------------------------------
#define XS_STRIDE 56
#define WS_STRIDE 132
#define XS_FLOATS (4 * 128 * XS_STRIDE)
#define WS_FLOATS (128 * WS_STRIDE)

__global__ __launch_bounds__(256) void conv_mma_kernel(
    const float* __restrict__ x, float* __restrict__ out)
{
    extern __shared__ float sm[];
    float* x_s = sm;               // [4 rows][128 ic][56]
    float* w_s = sm + XS_FLOATS;   // [128 oc][132]

    const int b   = blockIdx.z;
    const int rp  = blockIdx.y;
    const int ocg = blockIdx.x;
    const int tid = threadIdx.x;
    const int wid = tid >> 5, lane = tid & 31;
    const int warp_m = wid & 3;
    const int warp_n = wid >> 2;
    const int g = lane >> 2, q = lane & 3;

    for (int i = tid; i < 4 * 128 * 50; i += 256) {
        int r   = i / (128 * 50);
        int rem = i - r * 128 * 50;
        int ic  = rem / 50;
        int cc  = rem - ic * 50;
        int srow = (2 * rp - 1 + r + 48) % 48;
        int scol = (cc - 1 + 48) % 48;
        float v = x[((b * 128 + ic) * 48 + srow) * 48 + scol];
        ((uint32_t*)x_s)[(r * 128 + ic) * XS_STRIDE + cc] = to_tf32(v);
    }

    float c[2][6][4];
    #pragma unroll
    for (int mi = 0; mi < 2; mi++)
        #pragma unroll
        for (int j = 0; j < 6; j++)
            #pragma unroll
            for (int t = 0; t < 4; t++) c[mi][j][t] = 0.f;

    const uint32_t* xs = (const uint32_t*)x_s;
    const uint32_t* ws = (const uint32_t*)w_s;

    for (int tap = 0; tap < 9; tap++) {
        const int dr = tap / 3 - 1, dc = tap % 3 - 1;

        __syncthreads();
        {
            const float4* src = (const float4*)(g_w + (tap * 512 + ocg * 128) * 128);
            #pragma unroll
            for (int i = 0; i < 16; i++) {
                int e4  = tid + i * 256;
                int oc  = e4 >> 5;
                int ic4 = e4 & 31;
                float4 v = src[e4];
                *(float4*)&w_s[oc * WS_STRIDE + ic4 * 4] = v;
            }
        }
        __syncthreads();

        const int irow = warp_n + dr + 1;
        const int colb = dc + 1 + g;
        const uint32_t* xrow = xs + irow * 128 * XS_STRIDE;

        #pragma unroll
        for (int icc = 0; icc < 16; icc++) {
            const int ic0 = icc * 8;
            uint32_t a[2][4];
            #pragma unroll
            for (int mi = 0; mi < 2; mi++) {
                int r0 = (warp_m * 32 + mi * 16 + g) * WS_STRIDE + ic0 + q;
                a[mi][0] = ws[r0];
                a[mi][1] = ws[r0 + 8 * WS_STRIDE];
                a[mi][2] = ws[r0 + 4];
                a[mi][3] = ws[r0 + 8 * WS_STRIDE + 4];
            }
            #pragma unroll
            for (int j = 0; j < 6; j++) {
                uint32_t b0 = xrow[(ic0 + q) * XS_STRIDE + colb + j * 8];
                uint32_t b1 = xrow[(ic0 + q + 4) * XS_STRIDE + colb + j * 8];
                mma_tf32(c[0][j], a[0], b0, b1);
                mma_tf32(c[1][j], a[1], b0, b1);
            }
        }
    }

    const int orow = 2 * rp + warp_n;
    const int spat = orow * 48;
    #pragma unroll
    for (int mi = 0; mi < 2; mi++) {
        int oc_l = ocg * 128 + warp_m * 32 + mi * 16 + g;
        float* p = (oc_l < 128)
            ? out   + (size_t)(b * 256 + oc_l) * N_SP
            : g_qkv + (size_t)(b * 384 + oc_l - 128) * N_SP;
        float* p8 = p + 8 * N_SP;
        #pragma unroll
        for (int j = 0; j < 6; j++) {
            int col = j * 8 + 2 * q;
            *(float2*)&p [spat + col] = make_float2(c[mi][j][0], c[mi][j][1]);
            *(float2*)&p8[spat + col] = make_float2(c[mi][j][2], c[mi][j][3]);
        }
    }
}

// ---------------------------------------------------------------------------
// Kernel 2: flash attention on tensor cores (tf32).
// CTA = 128 queries x one (b,h). 8 warps, warp = 16 queries.
// Output stored (b,h,n,d)-CONTIGUOUS: matches the reference's raw reshape.
// ---------------------------------------------------------------------------
#define KS_STRIDE 136   // k_s read as [ch=q][key=g]  -> stride%32==8
#define VS_STRIDE 132   // v_s read as [dv=g][key=q]  -> stride%32==4
#define PS_STRIDE 132   // p_s read as [row=g][key=q] -> stride%32==4

__global__ __launch_bounds__(256, 2) void attn_mma_kernel()
{
    extern __shared__ float sm[];
    float* k_s = sm;                                  // [16][136]
    float* v_s = sm + 16 * KS_STRIDE;                 // [16][132]
    float* p_s = sm + 16 * KS_STRIDE + 16 * VS_STRIDE;// [8][16][132]

    const int b = blockIdx.z, h = blockIdx.y, qt = blockIdx.x;
    const int tid = threadIdx.x, wid = tid >> 5, lane = tid & 31;
    const int g = lane >> 2, q = lane & 3;
    const int qbase = qt * 128 + wid * 16;

    const float* qptr = g_qkv + (size_t)(b * 384 + h * 16) * N_SP;
    const float* kptr = g_qkv + (size_t)(b * 384 + 128 + h * 16) * N_SP;
    const float* vptr = g_qkv + (size_t)(b * 384 + 256 + h * 16) * N_SP;

    const float qscale = 0.25f * 1.4426950408889634f;  // dk^-0.5 * log2(e)

    // Q fragments (A of S-mma): A[query m=16][ch k=16], two k-steps
    uint32_t qa[2][4];
    #pragma unroll
    for (int s = 0; s < 2; s++) {
        qa[s][0] = to_tf32(qptr[(s * 8 + q)     * N_SP + qbase + g]     * qscale);
        qa[s][1] = to_tf32(qptr[(s * 8 + q)     * N_SP + qbase + g + 8] * qscale);
        qa[s][2] = to_tf32(qptr[(s * 8 + q + 4) * N_SP + qbase + g]     * qscale);
        qa[s][3] = to_tf32(qptr[(s * 8 + q + 4) * N_SP + qbase + g + 8] * qscale);
    }

    float m_g = -INFINITY, m_g8 = -INFINITY, l_g = 0.f, l_g8 = 0.f;
    float o[2][4];
    #pragma unroll
    for (int nt = 0; nt < 2; nt++)
        #pragma unroll
        for (int t = 0; t < 4; t++) o[nt][t] = 0.f;

    uint32_t* pw = (uint32_t*)(p_s + wid * 16 * PS_STRIDE);
    const uint32_t* ks32 = (const uint32_t*)k_s;
    const uint32_t* vs32 = (const uint32_t*)v_s;

    for (int kt = 0; kt < 18; kt++) {
        __syncthreads();
        #pragma unroll
        for (int it = 0; it < 8; it++) {
            int i  = tid + it * 256;           // 2048 elements
            int ch = i >> 7, key = i & 127;
            ((uint32_t*)k_s)[ch * KS_STRIDE + key] =
                to_tf32(kptr[ch * N_SP + kt * 128 + key]);
            ((uint32_t*)v_s)[ch * VS_STRIDE + key] =
                to_tf32(vptr[ch * N_SP + kt * 128 + key]);
        }
        __syncthreads();

        // ---- S = Q K^T : 16 n-tiles x 2 k-steps ----
        float cs[16][4];
        #pragma unroll
        for (int j = 0; j < 16; j++)
            #pragma unroll
            for (int t = 0; t < 4; t++) cs[j][t] = 0.f;

        #pragma unroll
        for (int s = 0; s < 2; s++)
            #pragma unroll
            for (int j = 0; j < 16; j++) {
                uint32_t b0 = ks32[(s * 8 + q)     * KS_STRIDE + j * 8 + g];
                uint32_t b1 = ks32[(s * 8 + q + 4) * KS_STRIDE + j * 8 + g];
                mma_tf32(cs[j], qa[s], b0, b1);
            }

        // ---- online softmax (base-2) ----
        float mt_g = -INFINITY, mt_g8 = -INFINITY;
        #pragma unroll
        for (int j = 0; j < 16; j++) {
            mt_g  = fmaxf(mt_g,  fmaxf(cs[j][0], cs[j][1]));
            mt_g8 = fmaxf(mt_g8, fmaxf(cs[j][2], cs[j][3]));
        }
        mt_g  = fmaxf(mt_g,  __shfl_xor_sync(0xffffffffu, mt_g, 1));
        mt_g  = fmaxf(mt_g,  __shfl_xor_sync(0xffffffffu, mt_g, 2));
        mt_g8 = fmaxf(mt_g8, __shfl_xor_sync(0xffffffffu, mt_g8, 1));
        mt_g8 = fmaxf(mt_g8, __shfl_xor_sync(0xffffffffu, mt_g8, 2));

        float mn_g  = fmaxf(m_g,  mt_g);
        float mn_g8 = fmaxf(m_g8, mt_g8);
        float a_g   = exp2f(m_g  - mn_g);
        float a_g8  = exp2f(m_g8 - mn_g8);

        float s_g = 0.f, s_g8 = 0.f;
        #pragma unroll
        for (int j = 0; j < 16; j++) {
            float p0 = exp2f(cs[j][0] - mn_g);
            float p1 = exp2f(cs[j][1] - mn_g);
            float p2 = exp2f(cs[j][2] - mn_g8);
            float p3 = exp2f(cs[j][3] - mn_g8);
            s_g  += p0 + p1;
            s_g8 += p2 + p3;
            pw[g       * PS_STRIDE + j * 8 + 2 * q]     = to_tf32(p0);
            pw[g       * PS_STRIDE + j * 8 + 2 * q + 1] = to_tf32(p1);
            pw[(g + 8) * PS_STRIDE + j * 8 + 2 * q]     = to_tf32(p2);
            pw[(g + 8) * PS_STRIDE + j * 8 + 2 * q + 1] = to_tf32(p3);
        }
        s_g  += __shfl_xor_sync(0xffffffffu, s_g, 1);
        s_g  += __shfl_xor_sync(0xffffffffu, s_g, 2);
        s_g8 += __shfl_xor_sync(0xffffffffu, s_g8, 1);
        s_g8 += __shfl_xor_sync(0xffffffffu, s_g8, 2);

        l_g  = l_g  * a_g  + s_g;
        l_g8 = l_g8 * a_g8 + s_g8;
        #pragma unroll
        for (int nt = 0; nt < 2; nt++) {
            o[nt][0] *= a_g;  o[nt][1] *= a_g;
            o[nt][2] *= a_g8; o[nt][3] *= a_g8;
        }
        m_g = mn_g; m_g8 = mn_g8;
        __syncwarp();

        // ---- O += P V^T : 2 n-tiles (dv) x 16 k-steps ----
        #pragma unroll
        for (int ks = 0; ks < 16; ks++) {
            uint32_t a[4];
            a[0] = pw[g       * PS_STRIDE + ks * 8 + q];
            a[1] = pw[(g + 8) * PS_STRIDE + ks * 8 + q];
            a[2] = pw[g       * PS_STRIDE + ks * 8 + q + 4];
            a[3] = pw[(g + 8) * PS_STRIDE + ks * 8 + q + 4];
            #pragma unroll
            for (int nt = 0; nt < 2; nt++) {
                uint32_t b0 = vs32[(nt * 8 + g) * VS_STRIDE + ks * 8 + q];
                uint32_t b1 = vs32[(nt * 8 + g) * VS_STRIDE + ks * 8 + q + 4];
                mma_tf32(o[nt], a, b0, b1);
            }
        }
        __syncwarp();
    }

    // ---- epilogue: normalize, store (b,h,n,d)-CONTIGUOUS (raw-reshape layout)
    const float il_g = 1.f / l_g, il_g8 = 1.f / l_g8;
    const size_t nb = (size_t)(b * 8 + h) * N_SP;
    #pragma unroll
    for (int nt = 0; nt < 2; nt++) {
        float* d0 = g_attn + (nb + qbase + g)     * 16 + nt * 8 + 2 * q;
        float* d8 = g_attn + (nb + qbase + g + 8) * 16 + nt * 8 + 2 * q;
        *(float2*)d0 = make_float2(o[nt][0] * il_g,  o[nt][1] * il_g);
        *(float2*)d8 = make_float2(o[nt][2] * il_g8, o[nt][3] * il_g8);
    }
}

// ---------------------------------------------------------------------------
// Kernel 3: 1x1 projection as tf32 mma GEMM: C[128oc,128n] = W[128,128]*A[128,n]
// A = g_attn reinterpreted as (b, 128ch, N)  (the raw reshape).
// ---------------------------------------------------------------------------
#define PW_STRIDE 132   // w_s read [oc=g][ic=q]
#define PA_STRIDE 136   // a_s read [ic=q][n=g]

__global__ __launch_bounds__(256) void proj_mma_kernel(
    const float* __restrict__ w_out, float* __restrict__ out)
{
    extern __shared__ float sm[];
    float* w_s = sm;                   // [128][132]
    float* a_s = sm + 128 * PW_STRIDE; // [128][136]

    const int b  = blockIdx.y;
    const int n0 = blockIdx.x * 128;
    const int tid = threadIdx.x, wid = tid >> 5, lane = tid & 31;
    const int g = lane >> 2, q = lane & 3;

    for (int i = tid; i < 16384; i += 256) {
        int oc = i >> 7, ic = i & 127;
        ((uint32_t*)w_s)[oc * PW_STRIDE + ic] = to_tf32(w_out[i]);
    }
    for (int i = tid; i < 16384; i += 256) {
        int ic = i >> 7, j = i & 127;
        ((uint32_t*)a_s)[ic * PA_STRIDE + j] =
            to_tf32(g_attn[(size_t)(b * 128 + ic) * N_SP + n0 + j]);
    }
    __syncthreads();

    const uint32_t* ws = (const uint32_t*)w_s;
    const uint32_t* as = (const uint32_t*)a_s;

    float c[16][4];
    #pragma unroll
    for (int j = 0; j < 16; j++)
        #pragma unroll
        for (int t = 0; t < 4; t++) c[j][t] = 0.f;

    #pragma unroll
    for (int ks = 0; ks < 16; ks++) {
        uint32_t a[4];
        int r0 = (wid * 16 + g) * PW_STRIDE + ks * 8 + q;
        a[0] = ws[r0];
        a[1] = ws[r0 + 8 * PW_STRIDE];
        a[2] = ws[r0 + 4];
        a[3] = ws[r0 + 8 * PW_STRIDE + 4];
        #pragma unroll
        for (int j = 0; j < 16; j++) {
            uint32_t b0 = as[(ks * 8 + q)     * PA_STRIDE + j * 8 + g];
            uint32_t b1 = as[(ks * 8 + q + 4) * PA_STRIDE + j * 8 + g];
            mma_tf32(c[j], a, b0, b1);
        }
    }

    #pragma unroll
    for (int j = 0; j < 16; j++) {
        int oc  = wid * 16 + g;
        int col = n0 + j * 8 + 2 * q;
        float* p  = out + (size_t)(b * 256 + 128 + oc) * N_SP;
        *(float2*)&p[col]            = make_float2(c[j][0], c[j][1]);
        *(float2*)&p[8 * N_SP + col] = make_float2(c[j][2], c[j][3]);
    }
}

// ---------------------------------------------------------------------------
extern "C" void kernel_launch(void* const* d_in, const int* in_sizes, int n_in,
                              void* d_out, int out_size)
{
    const float* x      = (const float*)d_in[0];
    const float* w_init = (const float*)d_in[1];
    const float* w_qkv  = (const float*)d_in[2];
    const float* w_out  = (const float*)d_in[3];
    float* out = (float*)d_out;

    const int conv_smem = (XS_FLOATS + WS_FLOATS) * 4;                       // 182272
    const int attn_smem = (16 * KS_STRIDE + 16 * VS_STRIDE + 8 * 16 * PS_STRIDE) * 4; // 84736
    const int proj_smem = (128 * PW_STRIDE + 128 * PA_STRIDE) * 4;           // 137216
    cudaFuncSetAttribute(conv_mma_kernel,
                         cudaFuncAttributeMaxDynamicSharedMemorySize, conv_smem);
    cudaFuncSetAttribute(attn_mma_kernel,
                         cudaFuncAttributeMaxDynamicSharedMemorySize, attn_smem);
    cudaFuncSetAttribute(proj_mma_kernel,
                         cudaFuncAttributeMaxDynamicSharedMemorySize, proj_smem);

    wprep_kernel<<<576, 1024>>>(w_init, w_qkv);

    dim3 cg(4, 24, 4);
    conv_mma_kernel<<<cg, 256, conv_smem>>>(x, out);

    dim3 ag(18, 8, 4);
    attn_mma_kernel<<<ag, 256, attn_smem>>>();

    dim3 pg(18, 4);
    proj_mma_kernel<<<pg, 256, proj_smem>>>(w_out, out);
}

// round 5
// speedup vs baseline: 4.4594x; 1.4035x over previous
#include <cuda_runtime.h>
#include <cuda_bf16.h>
#include <cstdint>

// Scratch (allocation-free rule: __device__ globals)
__device__ float g_qkv[4 * 384 * 2304];   // (b, 384, N) : q=0..127, k=128..255, v=256..383
__device__ float g_attn[4 * 128 * 2304];  // (b,8,N,16) contiguous == (b,128,N) reinterpret
__device__ float g_w[9 * 2 * 32 * 8 * 32 * 4]; // packed conv weights (A-frag order)

#define N_SP 2304   // 48*48

__device__ __forceinline__ uint32_t to_tf32(float f) {
    uint32_t t;
    asm("cvt.rna.tf32.f32 %0, %1;" : "=r"(t) : "f"(f));
    return t;
}

__device__ __forceinline__ float fast_ex2(float v) {
    float r;
    asm("ex2.approx.ftz.f32 %0, %1;" : "=f"(r) : "f"(v));
    return r;
}

__device__ __forceinline__ void mma_tf32(float c[4], const uint32_t a[4],
                                         uint32_t b0, uint32_t b1)
{
    asm volatile(
        "mma.sync.aligned.m16n8k8.row.col.f32.tf32.tf32.f32 "
        "{%0,%1,%2,%3}, {%4,%5,%6,%7}, {%8,%9}, {%0,%1,%2,%3};"
        : "+f"(c[0]), "+f"(c[1]), "+f"(c[2]), "+f"(c[3])
        : "r"(a[0]), "r"(a[1]), "r"(a[2]), "r"(a[3]), "r"(b0), "r"(b1));
}

__device__ __forceinline__ void cp_async16(uint32_t smem_addr, const void* gptr) {
    asm volatile("cp.async.cg.shared.global [%0], [%1], 16;"
                 :: "r"(smem_addr), "l"(gptr));
}
#define CP_COMMIT() asm volatile("cp.async.commit_group;" ::: "memory")
#define CP_WAIT0()  asm volatile("cp.async.wait_group 0;" ::: "memory")

// ---------------------------------------------------------------------------
// Kernel 0: pack conv weights into mma-A-fragment order, tf32(RN).
// Layout: [tap 9][half 2][ob 32][icclo 8][lane 32][e 4]
//   g=lane>>2, q=lane&3 ; oc = ob*16 + g + (e&1)*8 ; ic = (half*8+icclo)*8 + q + ((e>>1)&1)*4
// ---------------------------------------------------------------------------
__global__ __launch_bounds__(1024) void wprep_kernel(
    const float* __restrict__ w_init, const float* __restrict__ w_qkv)
{
    int idx = blockIdx.x * 1024 + threadIdx.x;   // 589824 total
    int e     = idx & 3;
    int lane  = (idx >> 2) & 31;
    int icclo = (idx >> 7) & 7;
    int ob    = (idx >> 10) & 31;
    int half  = (idx >> 15) & 1;
    int tap   = idx >> 16;
    int g = lane >> 2, q = lane & 3;
    int oc = ob * 16 + g + (e & 1) * 8;
    int ic = (half * 8 + icclo) * 8 + q + ((e >> 1) & 1) * 4;
    float v = (oc < 128) ? w_init[(oc * 128 + ic) * 9 + tap]
                         : w_qkv[((oc - 128) * 128 + ic) * 9 + tap];
    ((uint32_t*)g_w)[idx] = to_tf32(v);
}

// ---------------------------------------------------------------------------
// Kernel 1: 3x3 circular conv, 9-tap implicit GEMM (tf32 mma).
// Weights streamed as 18 half-tap chunks, double-buffered via cp.async.
// ---------------------------------------------------------------------------
#define XS_STRIDE 56
#define XS_FLOATS (4 * 128 * XS_STRIDE)   // 28672 floats
#define WCHUNK    8192                    // floats per weight chunk (8 ob x 8 icc)

__global__ __launch_bounds__(256) void conv_mma_kernel(
    const float* __restrict__ x, float* __restrict__ out)
{
    extern __shared__ float sm[];
    float* x_s = sm;                 // [4 rows][128 ic][56]
    float* w_s = sm + XS_FLOATS;     // [2][8192]

    const int b   = blockIdx.z;
    const int rp  = blockIdx.y;
    const int ocg = blockIdx.x;
    const int tid = threadIdx.x;
    const int wid = tid >> 5, lane = tid & 31;
    const int warp_m = wid & 3;
    const int warp_n = wid >> 2;
    const int g = lane >> 2, q = lane & 3;

    const uint32_t ws_u32 = (uint32_t)__cvta_generic_to_shared(w_s);

    // stage weight chunk c into buffer c&1 (8 cp.async.128 per thread)
    auto stage_w = [&](int c) {
        const float4* src = (const float4*)(g_w + ((size_t)c * 32 + ocg * 8) * 1024);
        uint32_t dst = ws_u32 + (uint32_t)(c & 1) * (WCHUNK * 4);
        #pragma unroll
        for (int i = 0; i < 8; i++) {
            int e4 = tid + i * 256;
            cp_async16(dst + e4 * 16, src + e4);
        }
    };

    stage_w(0); CP_COMMIT();

    // stage x: 4 wrapped input rows, 128 ic, 50 cols (raw fp32; mma truncates)
    for (int i = tid; i < 4 * 128 * 50; i += 256) {
        int r   = i / (128 * 50);
        int rem = i - r * 128 * 50;
        int ic  = rem / 50;
        int cc  = rem - ic * 50;
        int srow = (2 * rp - 1 + r + 48) % 48;
        int scol = (cc - 1 + 48) % 48;
        x_s[(r * 128 + ic) * XS_STRIDE + cc] = x[((b * 128 + ic) * 48 + srow) * 48 + scol];
    }

    float c_acc[2][6][4];
    #pragma unroll
    for (int mi = 0; mi < 2; mi++)
        #pragma unroll
        for (int j = 0; j < 6; j++)
            #pragma unroll
            for (int t = 0; t < 4; t++) c_acc[mi][j][t] = 0.f;

    const uint32_t* xs = (const uint32_t*)x_s;

    for (int ch = 0; ch < 18; ch++) {
        CP_WAIT0();
        __syncthreads();
        if (ch < 17) { stage_w(ch + 1); CP_COMMIT(); }

        const int tap = ch >> 1, half = ch & 1;
        const int dr = tap / 3 - 1, dc = tap % 3 - 1;
        const int irow = warp_n + dr + 1;
        const int colb = dc + 1 + g;
        const uint32_t* xrow = xs + irow * 128 * XS_STRIDE;
        const float4* wbuf = (const float4*)(w_s + (ch & 1) * WCHUNK);

        #pragma unroll
        for (int icclo = 0; icclo < 8; icclo++) {
            const int ic0 = half * 64 + icclo * 8;
            uint32_t a[2][4];
            #pragma unroll
            for (int mi = 0; mi < 2; mi++) {
                float4 av = wbuf[((warp_m * 2 + mi) * 8 + icclo) * 32 + lane];
                a[mi][0] = __float_as_uint(av.x);
                a[mi][1] = __float_as_uint(av.y);
                a[mi][2] = __float_as_uint(av.z);
                a[mi][3] = __float_as_uint(av.w);
            }
            #pragma unroll
            for (int j = 0; j < 6; j++) {
                uint32_t b0 = xrow[(ic0 + q) * XS_STRIDE + colb + j * 8];
                uint32_t b1 = xrow[(ic0 + q + 4) * XS_STRIDE + colb + j * 8];
                mma_tf32(c_acc[0][j], a[0], b0, b1);
                mma_tf32(c_acc[1][j], a[1], b0, b1);
            }
        }
    }

    const int orow = 2 * rp + warp_n;
    const int spat = orow * 48;
    #pragma unroll
    for (int mi = 0; mi < 2; mi++) {
        int oc_l = ocg * 128 + warp_m * 32 + mi * 16 + g;
        float* p = (oc_l < 128)
            ? out   + (size_t)(b * 256 + oc_l) * N_SP
            : g_qkv + (size_t)(b * 384 + oc_l - 128) * N_SP;
        float* p8 = p + 8 * N_SP;
        #pragma unroll
        for (int j = 0; j < 6; j++) {
            int col = j * 8 + 2 * q;
            *(float2*)&p [spat + col] = make_float2(c_acc[mi][j][0], c_acc[mi][j][1]);
            *(float2*)&p8[spat + col] = make_float2(c_acc[mi][j][2], c_acc[mi][j][3]);
        }
    }
}

// ---------------------------------------------------------------------------
// Kernel 2: flash attention, tf32 mma, no-max softmax, shfl P-transpose,
// cp.async double-buffered K/V. CTA = 128 queries x one (b,h).
// ---------------------------------------------------------------------------
#define KS_STRIDE 136   // [ch][key], read [q][g] -> q*8+g conflict-free
#define VS_STRIDE 132   // [dv][key], read [g][q] -> g*4+q conflict-free
#define KBUF (16 * KS_STRIDE)
#define VBUF (16 * VS_STRIDE)

__global__ __launch_bounds__(256, 2) void attn_mma_kernel()
{
    extern __shared__ float sm[];
    float* k_s = sm;             // [2][16][136]
    float* v_s = sm + 2 * KBUF;  // [2][16][132]

    const int b = blockIdx.z, h = blockIdx.y, qt = blockIdx.x;
    const int tid = threadIdx.x, wid = tid >> 5, lane = tid & 31;
    const int g = lane >> 2, q = lane & 3;
    const int qbase = qt * 128 + wid * 16;

    const float* qptr = g_qkv + (size_t)(b * 384 + h * 16) * N_SP;
    const float* kptr = g_qkv + (size_t)(b * 384 + 128 + h * 16) * N_SP;
    const float* vptr = g_qkv + (size_t)(b * 384 + 256 + h * 16) * N_SP;

    const uint32_t ks_u32 = (uint32_t)__cvta_generic_to_shared(k_s);
    const uint32_t vs_u32 = (uint32_t)__cvta_generic_to_shared(v_s);

    // stage K/V tile kt into buffer kt&1 (4 cp.async.128 per thread)
    auto stage = [&](int kt) {
        uint32_t buf = (uint32_t)(kt & 1);
        #pragma unroll
        for (int it = 0; it < 2; it++) {
            int i  = tid + it * 256;           // 512 float4 per tensor
            int ch = i >> 5, k4 = i & 31;
            cp_async16(ks_u32 + (buf * KBUF + ch * KS_STRIDE + k4 * 4) * 4,
                       kptr + ch * N_SP + kt * 128 + k4 * 4);
            cp_async16(vs_u32 + (buf * VBUF + ch * VS_STRIDE + k4 * 4) * 4,
                       vptr + ch * N_SP + kt * 128 + k4 * 4);
        }
    };

    stage(0); CP_COMMIT();

    const float qscale = 0.25f * 1.4426950408889634f;  // dk^-0.5 * log2(e)
    uint32_t qa[2][4];
    #pragma unroll
    for (int s = 0; s < 2; s++) {
        qa[s][0] = to_tf32(qptr[(s * 8 + q)     * N_SP + qbase + g]     * qscale);
        qa[s][1] = to_tf32(qptr[(s * 8 + q)     * N_SP + qbase + g + 8] * qscale);
        qa[s][2] = to_tf32(qptr[(s * 8 + q + 4) * N_SP + qbase + g]     * qscale);
        qa[s][3] = to_tf32(qptr[(s * 8 + q + 4) * N_SP + qbase + g + 8] * qscale);
    }

    float sum_g = 0.f, sum_g8 = 0.f;
    float o[2][4];
    #pragma unroll
    for (int nt = 0; nt < 2; nt++)
        #pragma unroll
        for (int t = 0; t < 4; t++) o[nt][t] = 0.f;

    const unsigned qb = lane & ~3u;   // quad base lane
    const unsigned qh = q >> 1;
    const bool odd = (q & 1);

    for (int kt = 0; kt < 18; kt++) {
        CP_WAIT0();
        __syncthreads();
        if (kt < 17) { stage(kt + 1); CP_COMMIT(); }

        const uint32_t* ks32 = (const uint32_t*)(k_s + (kt & 1) * KBUF);
        const uint32_t* vs32 = (const uint32_t*)(v_s + (kt & 1) * VBUF);

        #pragma unroll
        for (int half = 0; half < 2; half++) {
            float cs[8][4];
            #pragma unroll
            for (int j = 0; j < 8; j++)
                #pragma unroll
                for (int t = 0; t < 4; t++) cs[j][t] = 0.f;

            #pragma unroll
            for (int s = 0; s < 2; s++)
                #pragma unroll
                for (int j = 0; j < 8; j++) {
                    int jc = (half * 8 + j) * 8 + g;
                    uint32_t b0 = ks32[(s * 8 + q)     * KS_STRIDE + jc];
                    uint32_t b1 = ks32[(s * 8 + q + 4) * KS_STRIDE + jc];
                    mma_tf32(cs[j], qa[s], b0, b1);
                }

            #pragma unroll
            for (int j = 0; j < 8; j++) {
                float p0 = fast_ex2(cs[j][0]);
                float p1 = fast_ex2(cs[j][1]);
                float p2 = fast_ex2(cs[j][2]);
                float p3 = fast_ex2(cs[j][3]);
                sum_g  += p0 + p1;
                sum_g8 += p2 + p3;

                // quad shuffle: C-frag (rows g,g+8; cols 2q,2q+1) -> A-frag
                float s00 = __shfl_sync(0xffffffffu, p0, qb + qh);
                float s01 = __shfl_sync(0xffffffffu, p1, qb + qh);
                float s20 = __shfl_sync(0xffffffffu, p0, qb + qh + 2);
                float s21 = __shfl_sync(0xffffffffu, p1, qb + qh + 2);
                float s10 = __shfl_sync(0xffffffffu, p2, qb + qh);
                float s11 = __shfl_sync(0xffffffffu, p3, qb + qh);
                float s30 = __shfl_sync(0xffffffffu, p2, qb + qh + 2);
                float s31 = __shfl_sync(0xffffffffu, p3, qb + qh + 2);
                uint32_t a[4];
                a[0] = __float_as_uint(odd ? s01 : s00);
                a[1] = __float_as_uint(odd ? s11 : s10);
                a[2] = __float_as_uint(odd ? s21 : s20);
                a[3] = __float_as_uint(odd ? s31 : s30);

                const int ksx = (half * 8 + j) * 8;
                mma_tf32(o[0], a, vs32[g       * VS_STRIDE + ksx + q],
                                  vs32[g       * VS_STRIDE + ksx + q + 4]);
                mma_tf32(o[1], a, vs32[(8 + g) * VS_STRIDE + ksx + q],
                                  vs32[(8 + g) * VS_STRIDE + ksx + q + 4]);
            }
        }
    }

    // quad-reduce the softmax denominators
    sum_g  += __shfl_xor_sync(0xffffffffu, sum_g, 1);
    sum_g  += __shfl_xor_sync(0xffffffffu, sum_g, 2);
    sum_g8 += __shfl_xor_sync(0xffffffffu, sum_g8, 1);
    sum_g8 += __shfl_xor_sync(0xffffffffu, sum_g8, 2);
    const float il_g = 1.f / sum_g, il_g8 = 1.f / sum_g8;

    const size_t nb = (size_t)(b * 8 + h) * N_SP;
    #pragma unroll
    for (int nt = 0; nt < 2; nt++) {
        float* d0 = g_attn + (nb + qbase + g)     * 16 + nt * 8 + 2 * q;
        float* d8 = g_attn + (nb + qbase + g + 8) * 16 + nt * 8 + 2 * q;
        *(float2*)d0 = make_float2(o[nt][0] * il_g,  o[nt][1] * il_g);
        *(float2*)d8 = make_float2(o[nt][2] * il_g8, o[nt][3] * il_g8);
    }
}

// ---------------------------------------------------------------------------
// Kernel 3: 1x1 projection, tf32 mma: C[128oc,64n] = W[128,128]*A[128,64n]
// ---------------------------------------------------------------------------
#define PW_STRIDE 132   // w_s read [g][q] -> g*4+q conflict-free
#define PA_STRIDE 72    // a_s read [q][g] -> q*8+g conflict-free

__global__ __launch_bounds__(256) void proj_mma_kernel(
    const float* __restrict__ w_out, float* __restrict__ out)
{
    extern __shared__ float sm[];
    float* w_s = sm;                   // [128][132]
    float* a_s = sm + 128 * PW_STRIDE; // [128][72]

    const int b  = blockIdx.y;
    const int n0 = blockIdx.x * 64;
    const int tid = threadIdx.x, wid = tid >> 5, lane = tid & 31;
    const int g = lane >> 2, q = lane & 3;

    // stage W (4096 float4) and A (2048 float4), raw fp32
    const float4* wsrc = (const float4*)w_out;
    #pragma unroll
    for (int i = 0; i < 16; i++) {
        int e4 = tid + i * 256;
        int oc = e4 >> 5, ic4 = e4 & 31;
        *(float4*)&w_s[oc * PW_STRIDE + ic4 * 4] = wsrc[e4];
    }
    #pragma unroll
    for (int i = 0; i < 8; i++) {
        int e4 = tid + i * 256;
        int ic = e4 >> 4, c4 = e4 & 15;
        *(float4*)&a_s[ic * PA_STRIDE + c4 * 4] =
            *(const float4*)&g_attn[(size_t)(b * 128 + ic) * N_SP + n0 + c4 * 4];
    }
    __syncthreads();

    const uint32_t* ws = (const uint32_t*)w_s;
    const uint32_t* as = (const uint32_t*)a_s;

    float c[8][4];
    #pragma unroll
    for (int j = 0; j < 8; j++)
        #pragma unroll
        for (int t = 0; t < 4; t++) c[j][t] = 0.f;

    #pragma unroll
    for (int ks = 0; ks < 16; ks++) {
        uint32_t a[4];
        int r0 = (wid * 16 + g) * PW_STRIDE + ks * 8 + q;
        a[0] = ws[r0];
        a[1] = ws[r0 + 8 * PW_STRIDE];
        a[2] = ws[r0 + 4];
        a[3] = ws[r0 + 8 * PW_STRIDE + 4];
        #pragma unroll
        for (int j = 0; j < 8; j++) {
            uint32_t b0 = as[(ks * 8 + q)     * PA_STRIDE + j * 8 + g];
            uint32_t b1 = as[(ks * 8 + q + 4) * PA_STRIDE + j * 8 + g];
            mma_tf32(c[j], a, b0, b1);
        }
    }

    #pragma unroll
    for (int j = 0; j < 8; j++) {
        int oc  = wid * 16 + g;
        int col = n0 + j * 8 + 2 * q;
        float* p = out + (size_t)(b * 256 + 128 + oc) * N_SP;
        *(float2*)&p[col]            = make_float2(c[j][0], c[j][1]);
        *(float2*)&p[8 * N_SP + col] = make_float2(c[j][2], c[j][3]);
    }
}

// ---------------------------------------------------------------------------
extern "C" void kernel_launch(void* const* d_in, const int* in_sizes, int n_in,
                              void* d_out, int out_size)
{
    const float* x      = (const float*)d_in[0];
    const float* w_init = (const float*)d_in[1];
    const float* w_qkv  = (const float*)d_in[2];
    const float* w_out  = (const float*)d_in[3];
    float* out = (float*)d_out;

    const int conv_smem = (XS_FLOATS + 2 * WCHUNK) * 4;          // 180224 B
    const int attn_smem = (2 * KBUF + 2 * VBUF) * 4;             // 34304 B
    const int proj_smem = (128 * PW_STRIDE + 128 * PA_STRIDE) * 4; // 104448 B
    cudaFuncSetAttribute(conv_mma_kernel,
                         cudaFuncAttributeMaxDynamicSharedMemorySize, conv_smem);
    cudaFuncSetAttribute(attn_mma_kernel,
                         cudaFuncAttributeMaxDynamicSharedMemorySize, attn_smem);
    cudaFuncSetAttribute(proj_mma_kernel,
                         cudaFuncAttributeMaxDynamicSharedMemorySize, proj_smem);

    wprep_kernel<<<576, 1024>>>(w_init, w_qkv);

    dim3 cg(4, 24, 4);
    conv_mma_kernel<<<cg, 256, conv_smem>>>(x, out);

    dim3 ag(18, 8, 4);
    attn_mma_kernel<<<ag, 256, attn_smem>>>();

    dim3 pg(36, 4);
    proj_mma_kernel<<<pg, 256, proj_smem>>>(w_out, out);
}

// round 6
// speedup vs baseline: 6.2576x; 1.4033x over previous
#include <cuda_runtime.h>
#include <cuda_bf16.h>
#include <cstdint>

// Scratch (allocation-free rule: __device__ globals)
__device__ float    g_qkv[4 * 384 * 2304];  // (b,384,N): q=0..127, k=128..255 (v unused)
__device__ uint32_t g_vbf[4 * 128 * 1152];  // V packed bf16x2 key-pairs: [b][vch][keypair]
__device__ float    g_attn[4 * 128 * 2304]; // (b,8,N,16) contiguous == (b,128,N) reinterpret
__device__ float    g_w[9 * 2 * 32 * 8 * 32 * 4]; // packed conv weights (A-frag order)

#define N_SP 2304   // 48*48

__device__ __forceinline__ uint32_t to_tf32(float f) {
    uint32_t t;
    asm("cvt.rna.tf32.f32 %0, %1;" : "=r"(t) : "f"(f));
    return t;
}

__device__ __forceinline__ float fast_ex2(float v) {
    float r;
    asm("ex2.approx.ftz.f32 %0, %1;" : "=f"(r) : "f"(v));
    return r;
}

__device__ __forceinline__ uint32_t pack_bf16(float hi, float lo) {
    uint32_t r;
    asm("cvt.rn.bf16x2.f32 %0, %1, %2;" : "=r"(r) : "f"(hi), "f"(lo));
    return r;
}

__device__ __forceinline__ void mma_tf32(float c[4], const uint32_t a[4],
                                         uint32_t b0, uint32_t b1)
{
    asm volatile(
        "mma.sync.aligned.m16n8k8.row.col.f32.tf32.tf32.f32 "
        "{%0,%1,%2,%3}, {%4,%5,%6,%7}, {%8,%9}, {%0,%1,%2,%3};"
        : "+f"(c[0]), "+f"(c[1]), "+f"(c[2]), "+f"(c[3])
        : "r"(a[0]), "r"(a[1]), "r"(a[2]), "r"(a[3]), "r"(b0), "r"(b1));
}

__device__ __forceinline__ void mma_bf16(float c[4], const uint32_t a[4],
                                         uint32_t b0, uint32_t b1)
{
    asm volatile(
        "mma.sync.aligned.m16n8k16.row.col.f32.bf16.bf16.f32 "
        "{%0,%1,%2,%3}, {%4,%5,%6,%7}, {%8,%9}, {%0,%1,%2,%3};"
        : "+f"(c[0]), "+f"(c[1]), "+f"(c[2]), "+f"(c[3])
        : "r"(a[0]), "r"(a[1]), "r"(a[2]), "r"(a[3]), "r"(b0), "r"(b1));
}

__device__ __forceinline__ void cp_async16(uint32_t smem_addr, const void* gptr) {
    asm volatile("cp.async.cg.shared.global [%0], [%1], 16;"
                 :: "r"(smem_addr), "l"(gptr));
}
#define CP_COMMIT() asm volatile("cp.async.commit_group;" ::: "memory")
#define CP_WAIT0()  asm volatile("cp.async.wait_group 0;" ::: "memory")

// ---------------------------------------------------------------------------
// Kernel 0: pack conv weights into mma-A-fragment order, tf32(RN).
// ---------------------------------------------------------------------------
__global__ __launch_bounds__(1024) void wprep_kernel(
    const float* __restrict__ w_init, const float* __restrict__ w_qkv)
{
    int idx = blockIdx.x * 1024 + threadIdx.x;   // 589824 total
    int e     = idx & 3;
    int lane  = (idx >> 2) & 31;
    int icclo = (idx >> 7) & 7;
    int ob    = (idx >> 10) & 31;
    int half  = (idx >> 15) & 1;
    int tap   = idx >> 16;
    int g = lane >> 2, q = lane & 3;
    int oc = ob * 16 + g + (e & 1) * 8;
    int ic = (half * 8 + icclo) * 8 + q + ((e >> 1) & 1) * 4;
    float v = (oc < 128) ? w_init[(oc * 128 + ic) * 9 + tap]
                         : w_qkv[((oc - 128) * 128 + ic) * 9 + tap];
    ((uint32_t*)g_w)[idx] = to_tf32(v);
}

// ---------------------------------------------------------------------------
// Kernel 1: 3x3 circular conv, 9-tap implicit GEMM (tf32 mma).
// V channels (oc 384..511) written packed bf16x2 to g_vbf.
// ---------------------------------------------------------------------------
#define XS_STRIDE 56
#define XS_FLOATS (4 * 128 * XS_STRIDE)   // 28672 floats
#define WCHUNK    8192                    // floats per weight chunk

__global__ __launch_bounds__(256) void conv_mma_kernel(
    const float* __restrict__ x, float* __restrict__ out)
{
    extern __shared__ float sm[];
    float* x_s = sm;                 // [4 rows][128 ic][56], col idx = scol+2
    float* w_s = sm + XS_FLOATS;     // [2][8192]

    const int b   = blockIdx.z;
    const int rp  = blockIdx.y;
    const int ocg = blockIdx.x;
    const int tid = threadIdx.x;
    const int wid = tid >> 5, lane = tid & 31;
    const int warp_m = wid & 3;
    const int warp_n = wid >> 2;
    const int g = lane >> 2, q = lane & 3;

    const uint32_t ws_u32 = (uint32_t)__cvta_generic_to_shared(w_s);

    auto stage_w = [&](int c) {
        const float4* src = (const float4*)(g_w + ((size_t)c * 32 + ocg * 8) * 1024);
        uint32_t dst = ws_u32 + (uint32_t)(c & 1) * (WCHUNK * 4);
        #pragma unroll
        for (int i = 0; i < 8; i++) {
            int e4 = tid + i * 256;
            cp_async16(dst + e4 * 16, src + e4);
        }
    };

    stage_w(0); CP_COMMIT();

    // stage x: 512 (row,ic) lines, 2 per thread; bulk float2 + 2 halo scalars
    #pragma unroll
    for (int rr = 0; rr < 2; rr++) {
        int rowid = tid + rr * 256;
        int r = rowid >> 7, ic = rowid & 127;
        int srow = (2 * rp - 1 + r + 48) % 48;
        const float* src = x + ((b * 128 + ic) * 48 + srow) * 48;
        float* dst = &x_s[(r * 128 + ic) * XS_STRIDE];
        #pragma unroll
        for (int t = 0; t < 24; t++)
            *(float2*)&dst[2 + 2 * t] = *(const float2*)&src[2 * t];
        dst[1]  = src[47];
        dst[50] = src[0];
    }

    float c_acc[2][6][4];
    #pragma unroll
    for (int mi = 0; mi < 2; mi++)
        #pragma unroll
        for (int j = 0; j < 6; j++)
            #pragma unroll
            for (int t = 0; t < 4; t++) c_acc[mi][j][t] = 0.f;

    const uint32_t* xs = (const uint32_t*)x_s;

    for (int ch = 0; ch < 18; ch++) {
        CP_WAIT0();
        __syncthreads();
        if (ch < 17) { stage_w(ch + 1); CP_COMMIT(); }

        const int tap = ch >> 1, half = ch & 1;
        const int dr = tap / 3 - 1, dc = tap % 3 - 1;
        const int irow = warp_n + dr + 1;
        const int colb = dc + 2 + g;
        const uint32_t* xrow = xs + irow * 128 * XS_STRIDE;
        const float4* wbuf = (const float4*)(w_s + (ch & 1) * WCHUNK);

        #pragma unroll
        for (int icclo = 0; icclo < 8; icclo++) {
            const int ic0 = half * 64 + icclo * 8;
            uint32_t a[2][4];
            #pragma unroll
            for (int mi = 0; mi < 2; mi++) {
                float4 av = wbuf[((warp_m * 2 + mi) * 8 + icclo) * 32 + lane];
                a[mi][0] = __float_as_uint(av.x);
                a[mi][1] = __float_as_uint(av.y);
                a[mi][2] = __float_as_uint(av.z);
                a[mi][3] = __float_as_uint(av.w);
            }
            #pragma unroll
            for (int j = 0; j < 6; j++) {
                uint32_t b0 = xrow[(ic0 + q) * XS_STRIDE + colb + j * 8];
                uint32_t b1 = xrow[(ic0 + q + 4) * XS_STRIDE + colb + j * 8];
                mma_tf32(c_acc[0][j], a[0], b0, b1);
                mma_tf32(c_acc[1][j], a[1], b0, b1);
            }
        }
    }

    const int orow = 2 * rp + warp_n;
    const int spat = orow * 48;
    #pragma unroll
    for (int mi = 0; mi < 2; mi++) {
        int oc_l = ocg * 128 + warp_m * 32 + mi * 16 + g;
        if (oc_l < 384) {
            float* p = (oc_l < 128)
                ? out   + (size_t)(b * 256 + oc_l) * N_SP
                : g_qkv + (size_t)(b * 384 + oc_l - 128) * N_SP;
            float* p8 = p + 8 * N_SP;
            #pragma unroll
            for (int j = 0; j < 6; j++) {
                int col = j * 8 + 2 * q;
                *(float2*)&p [spat + col] = make_float2(c_acc[mi][j][0], c_acc[mi][j][1]);
                *(float2*)&p8[spat + col] = make_float2(c_acc[mi][j][2], c_acc[mi][j][3]);
            }
        } else {
            int vch = oc_l - 384;
            uint32_t* v0 = g_vbf + (size_t)(b * 128 + vch) * 1152 + orow * 24;
            uint32_t* v8 = v0 + 8 * 1152;
            #pragma unroll
            for (int j = 0; j < 6; j++) {
                v0[j * 4 + q] = pack_bf16(c_acc[mi][j][1], c_acc[mi][j][0]);
                v8[j * 4 + q] = pack_bf16(c_acc[mi][j][3], c_acc[mi][j][2]);
            }
        }
    }
}

// ---------------------------------------------------------------------------
// Kernel 2: flash attention. S: tf32 mma (m16n8k8). PV: bf16 mma (m16n8k16)
// with C->A fragment pass-through (zero shuffles). No-max softmax.
// ---------------------------------------------------------------------------
#define KS_STRIDE 136    // K smem: [ch][key] fp32
#define VS2_STRIDE 68    // V smem: [dv][keypair] u32 bf16x2
#define KBUF (16 * KS_STRIDE)    // floats per K buffer
#define VBUF (16 * VS2_STRIDE)   // u32 per V buffer

__global__ __launch_bounds__(256, 2) void attn_mma_kernel()
{
    extern __shared__ float sm[];
    float*    k_s = sm;                          // [2][16][136]
    uint32_t* v_s = (uint32_t*)(sm + 2 * KBUF);  // [2][16][68]

    const int b = blockIdx.z, h = blockIdx.y, qt = blockIdx.x;
    const int tid = threadIdx.x, wid = tid >> 5, lane = tid & 31;
    const int g = lane >> 2, q = lane & 3;
    const int qbase = qt * 128 + wid * 16;

    const float*    qptr = g_qkv + (size_t)(b * 384 + h * 16) * N_SP;
    const float*    kptr = g_qkv + (size_t)(b * 384 + 128 + h * 16) * N_SP;
    const uint32_t* vptr = g_vbf + (size_t)(b * 128 + h * 16) * 1152;

    const uint32_t ks_u32 = (uint32_t)__cvta_generic_to_shared(k_s);
    const uint32_t vs_u32 = (uint32_t)__cvta_generic_to_shared(v_s);

    auto stage = [&](int kt) {
        uint32_t buf = (uint32_t)(kt & 1);
        #pragma unroll
        for (int it = 0; it < 2; it++) {
            int i  = tid + it * 256;           // 512 float4 for K
            int ch = i >> 5, k4 = i & 31;
            cp_async16(ks_u32 + (buf * KBUF + ch * KS_STRIDE + k4 * 4) * 4,
                       kptr + ch * N_SP + kt * 128 + k4 * 4);
        }
        {
            int ch = tid >> 4, kp4 = tid & 15;  // 256 x 16B for V (bf16 packed)
            cp_async16(vs_u32 + (buf * VBUF + ch * VS2_STRIDE + kp4 * 4) * 4,
                       vptr + ch * 1152 + kt * 64 + kp4 * 4);
        }
    };

    stage(0); CP_COMMIT();

    const float qscale = 0.25f * 1.4426950408889634f;  // dk^-0.5 * log2(e)
    uint32_t qa[2][4];
    #pragma unroll
    for (int s = 0; s < 2; s++) {
        qa[s][0] = to_tf32(qptr[(s * 8 + q)     * N_SP + qbase + g]     * qscale);
        qa[s][1] = to_tf32(qptr[(s * 8 + q)     * N_SP + qbase + g + 8] * qscale);
        qa[s][2] = to_tf32(qptr[(s * 8 + q + 4) * N_SP + qbase + g]     * qscale);
        qa[s][3] = to_tf32(qptr[(s * 8 + q + 4) * N_SP + qbase + g + 8] * qscale);
    }

    float sum_g = 0.f, sum_g8 = 0.f;
    float o[2][4];
    #pragma unroll
    for (int nt = 0; nt < 2; nt++)
        #pragma unroll
        for (int t = 0; t < 4; t++) o[nt][t] = 0.f;

    for (int kt = 0; kt < 18; kt++) {
        CP_WAIT0();
        __syncthreads();
        if (kt < 17) { stage(kt + 1); CP_COMMIT(); }

        const uint32_t* ks32 = (const uint32_t*)(k_s + (kt & 1) * KBUF);
        const uint32_t* vbuf = v_s + (kt & 1) * VBUF;

        #pragma unroll
        for (int kb = 0; kb < 8; kb++) {        // 16 keys per block
            float cs0[4] = {0.f, 0.f, 0.f, 0.f};
            float cs1[4] = {0.f, 0.f, 0.f, 0.f};
            #pragma unroll
            for (int s = 0; s < 2; s++) {
                int r0 = (s * 8 + q) * KS_STRIDE + kb * 16 + g;
                int r1 = (s * 8 + q + 4) * KS_STRIDE + kb * 16 + g;
                mma_tf32(cs0, qa[s], ks32[r0],     ks32[r1]);
                mma_tf32(cs1, qa[s], ks32[r0 + 8], ks32[r1 + 8]);
            }

            float p00 = fast_ex2(cs0[0]), p01 = fast_ex2(cs0[1]);
            float p02 = fast_ex2(cs0[2]), p03 = fast_ex2(cs0[3]);
            float p10 = fast_ex2(cs1[0]), p11 = fast_ex2(cs1[1]);
            float p12 = fast_ex2(cs1[2]), p13 = fast_ex2(cs1[3]);
            sum_g  += (p00 + p01) + (p10 + p11);
            sum_g8 += (p02 + p03) + (p12 + p13);

            // C-frag -> bf16 A-frag of m16n8k16 (pass-through, no shuffles)
            uint32_t a[4];
            a[0] = pack_bf16(p01, p00);   // {P[g][2q], P[g][2q+1]}
            a[1] = pack_bf16(p03, p02);   // rows g+8
            a[2] = pack_bf16(p11, p10);   // cols +8 (tile j=2kb+1)
            a[3] = pack_bf16(p13, p12);

            mma_bf16(o[0], a, vbuf[g * VS2_STRIDE + kb * 8 + q],
                              vbuf[g * VS2_STRIDE + kb * 8 + q + 4]);
            mma_bf16(o[1], a, vbuf[(8 + g) * VS2_STRIDE + kb * 8 + q],
                              vbuf[(8 + g) * VS2_STRIDE + kb * 8 + q + 4]);
        }
    }

    sum_g  += __shfl_xor_sync(0xffffffffu, sum_g, 1);
    sum_g  += __shfl_xor_sync(0xffffffffu, sum_g, 2);
    sum_g8 += __shfl_xor_sync(0xffffffffu, sum_g8, 1);
    sum_g8 += __shfl_xor_sync(0xffffffffu, sum_g8, 2);
    const float il_g = 1.f / sum_g, il_g8 = 1.f / sum_g8;

    const size_t nb = (size_t)(b * 8 + h) * N_SP;
    #pragma unroll
    for (int nt = 0; nt < 2; nt++) {
        float* d0 = g_attn + (nb + qbase + g)     * 16 + nt * 8 + 2 * q;
        float* d8 = g_attn + (nb + qbase + g + 8) * 16 + nt * 8 + 2 * q;
        *(float2*)d0 = make_float2(o[nt][0] * il_g,  o[nt][1] * il_g);
        *(float2*)d8 = make_float2(o[nt][2] * il_g8, o[nt][3] * il_g8);
    }
}

// ---------------------------------------------------------------------------
// Kernel 3: 1x1 projection, tf32 mma: C[128oc,64n] = W[128,128]*A[128,64n]
// ---------------------------------------------------------------------------
#define PW_STRIDE 132
#define PA_STRIDE 72

__global__ __launch_bounds__(256) void proj_mma_kernel(
    const float* __restrict__ w_out, float* __restrict__ out)
{
    extern __shared__ float sm[];
    float* w_s = sm;                   // [128][132]
    float* a_s = sm + 128 * PW_STRIDE; // [128][72]

    const int b  = blockIdx.y;
    const int n0 = blockIdx.x * 64;
    const int tid = threadIdx.x, wid = tid >> 5, lane = tid & 31;
    const int g = lane >> 2, q = lane & 3;

    const float4* wsrc = (const float4*)w_out;
    #pragma unroll
    for (int i = 0; i < 16; i++) {
        int e4 = tid + i * 256;
        int oc = e4 >> 5, ic4 = e4 & 31;
        *(float4*)&w_s[oc * PW_STRIDE + ic4 * 4] = wsrc[e4];
    }
    #pragma unroll
    for (int i = 0; i < 8; i++) {
        int e4 = tid + i * 256;
        int ic = e4 >> 4, c4 = e4 & 15;
        *(float4*)&a_s[ic * PA_STRIDE + c4 * 4] =
            *(const float4*)&g_attn[(size_t)(b * 128 + ic) * N_SP + n0 + c4 * 4];
    }
    __syncthreads();

    const uint32_t* ws = (const uint32_t*)w_s;
    const uint32_t* as = (const uint32_t*)a_s;

    float c[8][4];
    #pragma unroll
    for (int j = 0; j < 8; j++)
        #pragma unroll
        for (int t = 0; t < 4; t++) c[j][t] = 0.f;

    #pragma unroll
    for (int ks = 0; ks < 16; ks++) {
        uint32_t a[4];
        int r0 = (wid * 16 + g) * PW_STRIDE + ks * 8 + q;
        a[0] = ws[r0];
        a[1] = ws[r0 + 8 * PW_STRIDE];
        a[2] = ws[r0 + 4];
        a[3] = ws[r0 + 8 * PW_STRIDE + 4];
        #pragma unroll
        for (int j = 0; j < 8; j++) {
            uint32_t b0 = as[(ks * 8 + q)     * PA_STRIDE + j * 8 + g];
            uint32_t b1 = as[(ks * 8 + q + 4) * PA_STRIDE + j * 8 + g];
            mma_tf32(c[j], a, b0, b1);
        }
    }

    #pragma unroll
    for (int j = 0; j < 8; j++) {
        int oc  = wid * 16 + g;
        int col = n0 + j * 8 + 2 * q;
        float* p = out + (size_t)(b * 256 + 128 + oc) * N_SP;
        *(float2*)&p[col]            = make_float2(c[j][0], c[j][1]);
        *(float2*)&p[8 * N_SP + col] = make_float2(c[j][2], c[j][3]);
    }
}

// ---------------------------------------------------------------------------
extern "C" void kernel_launch(void* const* d_in, const int* in_sizes, int n_in,
                              void* d_out, int out_size)
{
    const float* x      = (const float*)d_in[0];
    const float* w_init = (const float*)d_in[1];
    const float* w_qkv  = (const float*)d_in[2];
    const float* w_out  = (const float*)d_in[3];
    float* out = (float*)d_out;

    const int conv_smem = (XS_FLOATS + 2 * WCHUNK) * 4;            // 180224 B
    const int attn_smem = (2 * KBUF) * 4 + (2 * VBUF) * 4;         // 26112 B
    const int proj_smem = (128 * PW_STRIDE + 128 * PA_STRIDE) * 4; // 104448 B
    cudaFuncSetAttribute(conv_mma_kernel,
                         cudaFuncAttributeMaxDynamicSharedMemorySize, conv_smem);
    cudaFuncSetAttribute(attn_mma_kernel,
                         cudaFuncAttributeMaxDynamicSharedMemorySize, attn_smem);
    cudaFuncSetAttribute(proj_mma_kernel,
                         cudaFuncAttributeMaxDynamicSharedMemorySize, proj_smem);

    wprep_kernel<<<576, 1024>>>(w_init, w_qkv);

    dim3 cg(4, 24, 4);
    conv_mma_kernel<<<cg, 256, conv_smem>>>(x, out);

    dim3 ag(18, 8, 4);
    attn_mma_kernel<<<ag, 256, attn_smem>>>();

    dim3 pg(36, 4);
    proj_mma_kernel<<<pg, 256, proj_smem>>>(w_out, out);
}